// round 1
// baseline (speedup 1.0000x reference)
#include <cuda_runtime.h>
#include <cuda_bf16.h>

#define NUM_DOCS   1000000
#define VOCAB      30522
#define NNZ        64000000
#define Q_NNZ      32
#define SHARDS     4
#define TOP_K      100
#define RPS        250000          // rows per shard
#define BUFCAP     20480           // candidate buffer per shard (mean ~16.8K, sigma ~130)
#define K2_THREADS 512
#define SLOTS      (BUFCAP / K2_THREADS)   // 40 register-cached keys per thread

// ---------------- device scratch (no runtime allocation allowed) ----------------
__device__ float g_scores[NUM_DOCS];
__device__ int   g_cand[SHARDS * BUFCAP];
__device__ int   g_cnt[SHARDS];
__device__ float g_top_s[SHARDS * TOP_K];
__device__ int   g_top_i[SHARDS * TOP_K];

// ---------------- K0: zero scores + counters (re-run every graph replay) --------
__global__ void zero_kernel() {
    int i = blockIdx.x * blockDim.x + threadIdx.x;
    if (i < NUM_DOCS / 4) {
        ((float4*)g_scores)[i] = make_float4(0.f, 0.f, 0.f, 0.f);
    }
    if (i < SHARDS) g_cnt[i] = 0;
}

// ---------------- K1: scoring --------------------------------------------------
// Dense query lives in SMEM (122 KB). doc_indices streamed as int4 (coalesced).
// doc_values loaded only on a query hit (~0.1% of elements).
__global__ void __launch_bounds__(1024) score_kernel(
    const float* __restrict__ dv,
    const int*   __restrict__ di,
    const float* __restrict__ qv,
    const int*   __restrict__ qi)
{
    extern __shared__ float q[];   // VOCAB floats
    for (int i = threadIdx.x; i < VOCAB; i += blockDim.x) q[i] = 0.0f;
    __syncthreads();
    if (threadIdx.x < Q_NNZ) atomicAdd(&q[qi[threadIdx.x]], qv[threadIdx.x]);
    __syncthreads();

    const int4* di4 = (const int4*)di;
    const int total4 = NNZ / 4;
    const int stride = gridDim.x * blockDim.x;
    for (int c = blockIdx.x * blockDim.x + threadIdx.x; c < total4; c += stride) {
        int4 v4 = di4[c];
        int idx[4] = {v4.x, v4.y, v4.z, v4.w};
        #pragma unroll
        for (int j = 0; j < 4; j++) {
            float qq = q[idx[j]];
            if (qq != 0.0f) {
                float contrib = dv[c * 4 + j] * qq;
                int doc = c >> 4;              // 16 int4 chunks per doc (64 nnz)
                float old = atomicAdd(&g_scores[doc], contrib);
                if (old == 0.0f && contrib > 0.0f) {   // exactly-once candidate append
                    int sh = doc / RPS;
                    int p = atomicAdd(&g_cnt[sh], 1);
                    if (p < BUFCAP) g_cand[sh * BUFCAP + p] = doc;
                }
            }
        }
    }
}

// ---------------- K2: per-shard exact top-100 ----------------------------------
__device__ __forceinline__ int block_count(int local, int* red) {
    int w = __reduce_add_sync(0xFFFFFFFFu, local);
    int warp = threadIdx.x >> 5;
    int lane = threadIdx.x & 31;
    if (lane == 0) red[warp] = w;
    __syncthreads();
    if (threadIdx.x == 0) {
        int t = 0;
        #pragma unroll
        for (int i = 0; i < K2_THREADS / 32; i++) t += red[i];
        red[32] = t;
    }
    __syncthreads();
    int total = red[32];
    __syncthreads();   // protect red[] before next iteration overwrites it
    return total;
}

__global__ void __launch_bounds__(K2_THREADS) topk_shard_kernel() {
    __shared__ int red[33];
    __shared__ unsigned long long s_sel[TOP_K];
    __shared__ int s_num;

    const int s = blockIdx.x;
    const int tid = threadIdx.x;
    int n = g_cnt[s];
    if (n > BUFCAP) n = BUFCAP;

    // Register-cache keys: (score_bits << 32) | (0xFFFFFFFF - local_doc)
    // higher key == higher score, tie -> lower doc index (matches lax.top_k)
    unsigned long long kx[SLOTS];
    #pragma unroll
    for (int k = 0; k < SLOTS; k++) {
        int i = tid + k * K2_THREADS;
        unsigned long long key = 0ull;
        if (i < n) {
            int doc = g_cand[s * BUFCAP + i];
            float sc = g_scores[doc];
            key = ((unsigned long long)__float_as_uint(sc) << 32)
                | (unsigned long long)(0xFFFFFFFFu - (unsigned)(doc - s * RPS));
        }
        kx[k] = key;
    }
    if (tid == 0) s_num = 0;
    __syncthreads();

    unsigned long long thr;
    if (n >= TOP_K) {
        // exact binary search for the 100th-largest key (keys are distinct)
        unsigned long long lo = 0ull, hi = 0x7F80000000000000ull;
        while (hi - lo > 1ull) {
            unsigned long long mid = lo + ((hi - lo) >> 1);
            int local = 0;
            #pragma unroll
            for (int k = 0; k < SLOTS; k++) local += (kx[k] >= mid) ? 1 : 0;
            int c = block_count(local, red);
            if (c >= TOP_K) lo = mid; else hi = mid;
        }
        thr = lo;   // exactly TOP_K keys are >= thr
    } else {
        thr = 1ull; // degenerate: select all real keys (never hit with this data)
    }

    // compact selected keys (unordered), then order by rank-counting
    #pragma unroll
    for (int k = 0; k < SLOTS; k++) {
        if (kx[k] >= thr) {   // pads are 0 < 1 <= thr, excluded
            int p = atomicAdd(&s_num, 1);
            if (p < TOP_K) s_sel[p] = kx[k];
        }
    }
    __syncthreads();
    int m = s_num; if (m > TOP_K) m = TOP_K;
    if (tid < TOP_K) {
        if (tid < m) {
            unsigned long long key = s_sel[tid];
            int rank = 0;
            for (int j = 0; j < m; j++) rank += (s_sel[j] > key) ? 1 : 0;
            g_top_s[s * TOP_K + rank] = __uint_as_float((unsigned)(key >> 32));
            g_top_i[s * TOP_K + rank] = s * RPS + (int)(0xFFFFFFFFu - (unsigned)(key & 0xFFFFFFFFull));
        } else {
            g_top_s[s * TOP_K + tid] = 0.0f;           // deterministic pad (unreachable)
            g_top_i[s * TOP_K + tid] = s * RPS + tid;
        }
    }
}

// ---------------- K3: merge 4x100 -> global top-100, write output --------------
__global__ void merge_kernel(float* __restrict__ out) {
    __shared__ unsigned long long k400[SHARDS * TOP_K];
    __shared__ float sc400[SHARDS * TOP_K];
    __shared__ int   id400[SHARDS * TOP_K];

    for (int p = threadIdx.x; p < SHARDS * TOP_K; p += blockDim.x) {
        float sc = g_top_s[p];
        // tie -> lower concat position, matching reference merge semantics
        k400[p] = ((unsigned long long)__float_as_uint(sc) << 32)
                | (unsigned long long)(0xFFFFFFFFu - (unsigned)p);
        sc400[p] = sc;
        id400[p] = g_top_i[p];
    }
    __syncthreads();
    for (int p = threadIdx.x; p < SHARDS * TOP_K; p += blockDim.x) {
        unsigned long long key = k400[p];
        int rank = 0;
        #pragma unroll 4
        for (int j = 0; j < SHARDS * TOP_K; j++) rank += (k400[j] > key) ? 1 : 0;
        if (rank < TOP_K) {
            out[rank]          = sc400[p];
            out[TOP_K + rank]  = (float)id400[p];
        }
    }
}

// ---------------- launch --------------------------------------------------------
extern "C" void kernel_launch(void* const* d_in, const int* in_sizes, int n_in,
                              void* d_out, int out_size) {
    const float* dv = (const float*)d_in[0];   // doc_values   [NNZ]
    const float* qv = (const float*)d_in[1];   // q_values     [Q_NNZ]
    const int*   di = (const int*)  d_in[2];   // doc_indices  [NNZ]
    /* d_in[3] = row_ids: redundant (row = i >> 6), never read */
    const int*   qi = (const int*)  d_in[4];   // q_indices    [Q_NNZ]
    float* out = (float*)d_out;

    cudaFuncSetAttribute(score_kernel,
                         cudaFuncAttributeMaxDynamicSharedMemorySize, VOCAB * 4);

    zero_kernel<<<(NUM_DOCS / 4 + 1023) / 1024, 1024>>>();
    score_kernel<<<148, 1024, VOCAB * 4>>>(dv, di, qv, qi);
    topk_shard_kernel<<<SHARDS, K2_THREADS>>>();
    merge_kernel<<<1, 128>>>(out);
}